// round 7
// baseline (speedup 1.0000x reference)
#include <cuda_runtime.h>
#include <math_constants.h>

#define NB   1024
#define NH   16384
#define SDIM 32
#define HID  64
#define NG   10
#define NK   4
#define GA   80

#define QT   64            // queries per block (8 per warp)
#define KT   128           // keys per tile
#define KROW 132           // padded row stride for K/V/P smem tiles
#define QROW 68            // padded row stride for Q tile
#define NSPLIT 2
#define KEYS_PER_CTA (NH / NSPLIT)      // 8192
#define NTILES (KEYS_PER_CTA / KT)      // 64
#define ATHREADS 256

// Scratch (no cudaMalloc allowed)
__device__ float g_enc_hT[NK * HID * NH];        // [k][d][h]
__device__ float g_enc_sT[NK * HID * NB];        // [k][d][b]
__device__ float g_VT[GA * NH];                  // [a][j]
__device__ float g_Opart[NSPLIT * NK * NB * GA]; // unnormalized partial O
__device__ float g_ml[NSPLIT * NK * NB * 2];     // (m, l) per split/k/row

// Packed dual-fp32 FMA / MUL (sm_103a f32x2 pipe)
__device__ __forceinline__ float2 ffma2(float2 a, float2 b, float2 c) {
    unsigned long long ua = *reinterpret_cast<unsigned long long*>(&a);
    unsigned long long ub = *reinterpret_cast<unsigned long long*>(&b);
    unsigned long long uc = *reinterpret_cast<unsigned long long*>(&c);
    unsigned long long ud;
    asm("fma.rn.f32x2 %0, %1, %2, %3;" : "=l"(ud) : "l"(ua), "l"(ub), "l"(uc));
    return *reinterpret_cast<float2*>(&ud);
}
__device__ __forceinline__ float2 fmul2(float2 a, float2 b) {
    unsigned long long ua = *reinterpret_cast<unsigned long long*>(&a);
    unsigned long long ub = *reinterpret_cast<unsigned long long*>(&b);
    unsigned long long ud;
    asm("mul.rn.f32x2 %0, %1, %2;" : "=l"(ud) : "l"(ua), "l"(ub));
    return *reinterpret_cast<float2*>(&ud);
}

__device__ __forceinline__ void cp16(float* dst, const float* src) {
    unsigned s = (unsigned)__cvta_generic_to_shared(dst);
    asm volatile("cp.async.cg.shared.global [%0], [%1], 16;\n" :: "r"(s), "l"(src));
}

// ---------------------------------------------------------------------------
// Encoder: x[nrows,32] -> outT[k][d][nrows] (TRANSPOSED), 3x (Linear+ReLU).
// ---------------------------------------------------------------------------
__global__ __launch_bounds__(256) void encoder_kernel(
    const float* __restrict__ x, float* __restrict__ outT, int nrows,
    const float* __restrict__ W0, const float* __restrict__ b0,
    const float* __restrict__ W1, const float* __restrict__ b1,
    const float* __restrict__ W2, const float* __restrict__ b2)
{
    const int k    = blockIdx.y;
    const int row0 = blockIdx.x * 64;
    const int tid  = threadIdx.x;
    const int o    = tid & 63;
    const int rr   = tid >> 6;

    __shared__ float smem[10240];
    float* xs  = smem;
    float* hs0 = smem + 2048;
    float* hs1 = smem + 6144;
    float* hs2 = smem;   // aliases xs+hs0 (dead by layer 2)

    for (int i = tid; i < 64 * SDIM; i += 256)
        xs[i] = x[(size_t)row0 * SDIM + i];
    __syncthreads();

    {
        float2 w[SDIM / 2];
        const float* Wp = W0 + (size_t)k * SDIM * HID + o;
        #pragma unroll
        for (int i = 0; i < SDIM / 2; i++)
            w[i] = make_float2(Wp[(2 * i) * HID], Wp[(2 * i + 1) * HID]);
        const float bias = b0[k * HID + o];
        #pragma unroll 4
        for (int r = rr; r < 64; r += 4) {
            const float2* xr = reinterpret_cast<const float2*>(xs + r * SDIM);
            float2 acc = make_float2(0.f, 0.f);
            #pragma unroll
            for (int i = 0; i < SDIM / 2; i++) acc = ffma2(xr[i], w[i], acc);
            hs0[r * HID + o] = fmaxf(acc.x + acc.y + bias, 0.f);
        }
    }
    __syncthreads();

    {
        float2 w[HID / 2];
        const float* Wp = W1 + (size_t)k * HID * HID + o;
        #pragma unroll
        for (int i = 0; i < HID / 2; i++)
            w[i] = make_float2(Wp[(2 * i) * HID], Wp[(2 * i + 1) * HID]);
        const float bias = b1[k * HID + o];
        #pragma unroll 4
        for (int r = rr; r < 64; r += 4) {
            const float2* hr = reinterpret_cast<const float2*>(hs0 + r * HID);
            float2 acc = make_float2(0.f, 0.f);
            #pragma unroll
            for (int i = 0; i < HID / 2; i++) acc = ffma2(hr[i], w[i], acc);
            hs1[r * HID + o] = fmaxf(acc.x + acc.y + bias, 0.f);
        }
    }
    __syncthreads();

    {
        float2 w[HID / 2];
        const float* Wp = W2 + (size_t)k * HID * HID + o;
        #pragma unroll
        for (int i = 0; i < HID / 2; i++)
            w[i] = make_float2(Wp[(2 * i) * HID], Wp[(2 * i + 1) * HID]);
        const float bias = b2[k * HID + o];
        #pragma unroll 4
        for (int r = rr; r < 64; r += 4) {
            const float2* hr = reinterpret_cast<const float2*>(hs1 + r * HID);
            float2 acc = make_float2(0.f, 0.f);
            #pragma unroll
            for (int i = 0; i < HID / 2; i++) acc = ffma2(hr[i], w[i], acc);
            hs2[r * 65 + o] = fmaxf(acc.x + acc.y + bias, 0.f);
        }
    }
    __syncthreads();

    for (int i = tid; i < 64 * 64; i += 256) {
        int h = i & 63, d = i >> 6;
        outT[((size_t)k * HID + d) * nrows + row0 + h] = hs2[h * 65 + d];
    }
}

// ---------------------------------------------------------------------------
// V transpose: g_VT[a][j] = V[j][a]
// ---------------------------------------------------------------------------
__global__ __launch_bounds__(256) void vtrans_kernel(const float* __restrict__ V)
{
    __shared__ float sm[128 * GA];
    const int j0 = blockIdx.x * 128;
    for (int i = threadIdx.x; i < 128 * GA; i += 256)
        sm[i] = V[(size_t)j0 * GA + i];
    __syncthreads();
    for (int i = threadIdx.x; i < 128 * GA; i += 256) {
        int a = i >> 7, j = i & 127;
        g_VT[(size_t)a * NH + j0 + j] = sm[j * GA + a];
    }
}

// ---------------------------------------------------------------------------
// Flash attention, split-K. Block = (qtile64, k, split). 8 warps x 8 queries.
// Scores: lane owns keys 4*lane..+3 (8q x 4k per thread, rank-1 over d).
// PV: lane = jh*16 + ah; 8q x 5a per thread over its 64-key j-half;
//     V read as deduped float4 (2-cyc floor), jh half selected in regs.
// Writes UNNORMALIZED partial O + (m,l) for the merge kernel.
// ---------------------------------------------------------------------------
__global__ __launch_bounds__(ATHREADS, 1) void attn_kernel()
{
    extern __shared__ float sm[];
    float* Qs   = sm;                      // HID x QROW
    float* Ksb0 = Qs + HID * QROW;         // HID x KROW (double buffered)
    float* Ksb1 = Ksb0 + HID * KROW;
    float* Vsb0 = Ksb1 + HID * KROW;       // GA x KROW (double buffered)
    float* Vsb1 = Vsb0 + GA * KROW;
    float* Ps   = Vsb1 + GA * KROW;        // QT x KROW

    const int k    = blockIdx.y;
    const int s    = blockIdx.z;
    const int q0   = blockIdx.x * QT;
    const int tid  = threadIdx.x;
    const int warp = tid >> 5;
    const int lane = tid & 31;
    const int ah   = lane & 15;
    const int jh   = lane >> 4;
    const int kb   = s * KEYS_PER_CTA;

    const float* Kg = g_enc_hT + (size_t)k * HID * NH;
    const float* Qg = g_enc_sT + (size_t)k * HID * NB;

    // Q tile [d][q], float4 coalesced
    for (int i = tid; i < HID * (QT / 4); i += ATHREADS) {
        int d = i >> 4, c = i & 15;
        *(float4*)(Qs + d * QROW + c * 4) =
            *(const float4*)(Qg + (size_t)d * NB + q0 + c * 4);
    }

    // prologue prefetch tile 0
    {
        #pragma unroll
        for (int it = 0; it < 8; it++) {
            int idx = tid + it * ATHREADS;
            int r = idx >> 5, c = idx & 31;
            cp16(Ksb0 + r * KROW + c * 4, Kg + (size_t)r * NH + kb + c * 4);
        }
        #pragma unroll
        for (int it = 0; it < 10; it++) {
            int idx = tid + it * ATHREADS;
            int r = idx >> 5, c = idx & 31;
            cp16(Vsb0 + r * KROW + c * 4, g_VT + (size_t)r * NH + kb + c * 4);
        }
        asm volatile("cp.async.commit_group;");
    }

    float m[8], l[8];
    #pragma unroll
    for (int qi = 0; qi < 8; qi++) { m[qi] = -CUDART_INF_F; l[qi] = 0.f; }
    float2 oacc[8][5];
    #pragma unroll
    for (int qi = 0; qi < 8; qi++)
        #pragma unroll
        for (int a = 0; a < 5; a++) oacc[qi][a] = make_float2(0.f, 0.f);

    for (int t = 0; t < NTILES; t++) {
        float* Kc = (t & 1) ? Ksb1 : Ksb0;
        float* Vc = (t & 1) ? Vsb1 : Vsb0;

        if (t + 1 < NTILES) {
            const int key0 = kb + (t + 1) * KT;
            float* Kn = (t & 1) ? Ksb0 : Ksb1;
            float* Vn = (t & 1) ? Vsb0 : Vsb1;
            #pragma unroll
            for (int it = 0; it < 8; it++) {
                int idx = tid + it * ATHREADS;
                int r = idx >> 5, c = idx & 31;
                cp16(Kn + r * KROW + c * 4, Kg + (size_t)r * NH + key0 + c * 4);
            }
            #pragma unroll
            for (int it = 0; it < 10; it++) {
                int idx = tid + it * ATHREADS;
                int r = idx >> 5, c = idx & 31;
                cp16(Vn + r * KROW + c * 4, g_VT + (size_t)r * NH + key0 + c * 4);
            }
            asm volatile("cp.async.commit_group;");
            asm volatile("cp.async.wait_group 1;");
        } else {
            asm volatile("cp.async.wait_group 0;");
        }
        __syncthreads();

        // ---- scores: 8q x 4k rank-1 over d; acc packed over key-pairs ----
        float2 aA[8], aB[8];
        #pragma unroll
        for (int qi = 0; qi < 8; qi++) {
            aA[qi] = make_float2(0.f, 0.f);
            aB[qi] = make_float2(0.f, 0.f);
        }
        const float* Kp = Kc + 4 * lane;
        const float* Qp = Qs + 8 * warp;
        #pragma unroll 4
        for (int d = 0; d < HID; d++) {
            float4 k4 = *(const float4*)(Kp + d * KROW);
            float4 qa = *(const float4*)(Qp + d * QROW);
            float4 qb = *(const float4*)(Qp + d * QROW + 4);
            float2 kA = make_float2(k4.x, k4.y);
            float2 kB = make_float2(k4.z, k4.w);
            float2 qd;
            qd = make_float2(qa.x, qa.x);
            aA[0] = ffma2(qd, kA, aA[0]); aB[0] = ffma2(qd, kB, aB[0]);
            qd = make_float2(qa.y, qa.y);
            aA[1] = ffma2(qd, kA, aA[1]); aB[1] = ffma2(qd, kB, aB[1]);
            qd = make_float2(qa.z, qa.z);
            aA[2] = ffma2(qd, kA, aA[2]); aB[2] = ffma2(qd, kB, aB[2]);
            qd = make_float2(qa.w, qa.w);
            aA[3] = ffma2(qd, kA, aA[3]); aB[3] = ffma2(qd, kB, aB[3]);
            qd = make_float2(qb.x, qb.x);
            aA[4] = ffma2(qd, kA, aA[4]); aB[4] = ffma2(qd, kB, aB[4]);
            qd = make_float2(qb.y, qb.y);
            aA[5] = ffma2(qd, kA, aA[5]); aB[5] = ffma2(qd, kB, aB[5]);
            qd = make_float2(qb.z, qb.z);
            aA[6] = ffma2(qd, kA, aA[6]); aB[6] = ffma2(qd, kB, aB[6]);
            qd = make_float2(qb.w, qb.w);
            aA[7] = ffma2(qd, kA, aA[7]); aB[7] = ffma2(qd, kB, aB[7]);
        }

        // ---- online softmax per query (warp-wide: 128 keys) ----
        #pragma unroll
        for (int qi = 0; qi < 8; qi++) {
            float s0 = aA[qi].x, s1 = aA[qi].y, s2 = aB[qi].x, s3 = aB[qi].y;
            float mx = fmaxf(fmaxf(s0, s1), fmaxf(s2, s3));
            #pragma unroll
            for (int off = 16; off > 0; off >>= 1)
                mx = fmaxf(mx, __shfl_xor_sync(0xffffffffu, mx, off));
            float nm = fmaxf(m[qi], mx);
            float c = __expf(m[qi] - nm);
            m[qi] = nm;
            float p0 = __expf(s0 - nm), p1 = __expf(s1 - nm);
            float p2 = __expf(s2 - nm), p3 = __expf(s3 - nm);
            float ts = (p0 + p1) + (p2 + p3);
            #pragma unroll
            for (int off = 16; off > 0; off >>= 1)
                ts += __shfl_xor_sync(0xffffffffu, ts, off);
            l[qi] = l[qi] * c + ts;
            *(float4*)(Ps + (8 * warp + qi) * KROW + 4 * lane) =
                make_float4(p0, p1, p2, p3);
            float2 cc = make_float2(c, c);
            #pragma unroll
            for (int a = 0; a < 5; a++) oacc[qi][a] = fmul2(oacc[qi][a], cc);
        }
        __syncwarp();   // Ps rows are warp-private

        // ---- PV: 8q x 5a per thread; V as deduped float4, jh-half in regs --
        const float* Pp = Ps + (8 * warp) * KROW + 2 * jh;
        const float* Vp = Vc + (5 * ah) * KROW;
        #pragma unroll 4
        for (int tt = 0; tt < 32; tt++) {
            float2 p[8];
            #pragma unroll
            for (int qi = 0; qi < 8; qi++)
                p[qi] = *(const float2*)(Pp + qi * KROW + 4 * tt);
            #pragma unroll
            for (int a = 0; a < 5; a++) {
                float4 v4 = *(const float4*)(Vp + a * KROW + 4 * tt);
                float2 vj = jh ? make_float2(v4.z, v4.w)
                               : make_float2(v4.x, v4.y);
                #pragma unroll
                for (int qi = 0; qi < 8; qi++)
                    oacc[qi][a] = ffma2(p[qi], vj, oacc[qi][a]);
            }
        }
        __syncthreads();   // all warps done with Kc/Vc before buffer reuse
    }

    // ---- epilogue: reduce jh halves, write UNNORMALIZED partials ----
    #pragma unroll
    for (int qi = 0; qi < 8; qi++) {
        const int row = q0 + 8 * warp + qi;
        float* Od = g_Opart + (((size_t)s * NK + k) * NB + row) * GA;
        #pragma unroll
        for (int a = 0; a < 5; a++) {
            float o = oacc[qi][a].x + oacc[qi][a].y;
            o += __shfl_xor_sync(0xffffffffu, o, 16);
            if (jh == 0) Od[5 * ah + a] = o;
        }
        if (lane == 0) {
            g_ml[(((size_t)s * NK + k) * NB + row) * 2 + 0] = m[qi];
            g_ml[(((size_t)s * NK + k) * NB + row) * 2 + 1] = l[qi];
        }
    }
}

// ---------------------------------------------------------------------------
// Merge: combine 2 key-splits (softmax merge) + k-combine in one pass.
// out[b,g,a] = sum_k softmax_k(assign[g,:]) * O_k[b,ga]
// ---------------------------------------------------------------------------
__global__ __launch_bounds__(256) void merge_kernel(
    const float* __restrict__ assign, float* __restrict__ out)
{
    int idx = blockIdx.x * 256 + threadIdx.x;
    if (idx >= NB * GA) return;
    int b  = idx / GA;
    int ga = idx - b * GA;
    int g  = ga >> 3;

    float aw[NK], mxw = -CUDART_INF_F;
    #pragma unroll
    for (int k = 0; k < NK; k++) {
        aw[k] = __ldg(assign + g * NK + k);
        mxw = fmaxf(mxw, aw[k]);
    }
    float wsum = 0.f;
    #pragma unroll
    for (int k = 0; k < NK; k++) {
        aw[k] = __expf(aw[k] - mxw);
        wsum += aw[k];
    }
    float winv = 1.f / wsum;

    float acc = 0.f;
    #pragma unroll
    for (int k = 0; k < NK; k++) {
        float m0 = g_ml[(((size_t)0 * NK + k) * NB + b) * 2 + 0];
        float l0 = g_ml[(((size_t)0 * NK + k) * NB + b) * 2 + 1];
        float m1 = g_ml[(((size_t)1 * NK + k) * NB + b) * 2 + 0];
        float l1 = g_ml[(((size_t)1 * NK + k) * NB + b) * 2 + 1];
        float M  = fmaxf(m0, m1);
        float w0 = __expf(m0 - M), w1 = __expf(m1 - M);
        float L  = l0 * w0 + l1 * w1;
        float O0 = g_Opart[(((size_t)0 * NK + k) * NB + b) * GA + ga];
        float O1 = g_Opart[(((size_t)1 * NK + k) * NB + b) * GA + ga];
        acc += aw[k] * ((O0 * w0 + O1 * w1) / L);
    }
    out[idx] = acc * winv;
}

// ---------------------------------------------------------------------------
extern "C" void kernel_launch(void* const* d_in, const int* in_sizes, int n_in,
                              void* d_out, int out_size)
{
    (void)in_sizes; (void)n_in; (void)out_size;
    const float* state  = (const float*)d_in[0];
    const float* hist   = (const float*)d_in[1];
    const float* jah    = (const float*)d_in[2];
    const float* W0 = (const float*)d_in[3];
    const float* b0 = (const float*)d_in[4];
    const float* W1 = (const float*)d_in[5];
    const float* b1 = (const float*)d_in[6];
    const float* W2 = (const float*)d_in[7];
    const float* b2 = (const float*)d_in[8];
    const float* assign = (const float*)d_in[9];
    float* out = (float*)d_out;

    float* enc_hT_p = nullptr;
    float* enc_sT_p = nullptr;
    cudaGetSymbolAddress((void**)&enc_hT_p, g_enc_hT);
    cudaGetSymbolAddress((void**)&enc_sT_p, g_enc_sT);

    vtrans_kernel<<<NH / 128, 256>>>(jah);
    encoder_kernel<<<dim3(NH / 64, NK), 256>>>(hist, enc_hT_p, NH,
                                               W0, b0, W1, b1, W2, b2);
    encoder_kernel<<<dim3(NB / 64, NK), 256>>>(state, enc_sT_p, NB,
                                               W0, b0, W1, b1, W2, b2);

    const int smem_bytes =
        (HID * QROW + 2 * HID * KROW + 2 * GA * KROW + QT * KROW) *
        (int)sizeof(float);
    cudaFuncSetAttribute(attn_kernel,
                         cudaFuncAttributeMaxDynamicSharedMemorySize, smem_bytes);
    attn_kernel<<<dim3(NB / QT, NK, NSPLIT), ATHREADS, smem_bytes>>>();

    merge_kernel<<<(NB * GA + 255) / 256, 256>>>(assign, out);
}

// round 9
// speedup vs baseline: 4.0520x; 4.0520x over previous
#include <cuda_runtime.h>
#include <cuda_bf16.h>
#include <math_constants.h>
#include <cstdint>

#define NB   1024
#define NH   16384
#define SDIM 32
#define HID  64
#define NK   4
#define GA   80

#define MQ   128
#define KT   128
#define NSPLIT 4
#define KEYS_PER_CTA (NH / NSPLIT)   // 4096
#define TILES (KEYS_PER_CTA / KT)    // 32

#define KROWB 144    // K/Q smem row stride bytes (64 bf16 + 16B pad)
#define VROWB 272    // V smem row stride bytes (128 bf16 + 16B pad)

// smem byte offsets
#define SM_MHAT 0
#define SM_KH0  1024
#define SM_KL0  (SM_KH0 + 128 * KROWB)     // 19456
#define SM_KH1  (SM_KL0 + 128 * KROWB)     // 37888
#define SM_KL1  (SM_KH1 + 128 * KROWB)     // 56320
#define SM_VH0  (SM_KL1 + 128 * KROWB)     // 74752
#define SM_VL0  (SM_VH0 + 80 * VROWB)      // 96512
#define SM_VH1  (SM_VL0 + 80 * VROWB)      // 118272
#define SM_VL1  (SM_VH1 + 80 * VROWB)      // 140032
#define SM_TOTAL (SM_VL1 + 80 * VROWB)     // 161792

// global scratch
__device__ float         g_enc_s[NK * NB * HID];
__device__ __nv_bfloat16 g_Khi[NK * NH * HID];
__device__ __nv_bfloat16 g_Klo[NK * NH * HID];
__device__ __nv_bfloat16 g_VThi[GA * NH];
__device__ __nv_bfloat16 g_VTlo[GA * NH];
__device__ float         g_Kmax[NK];
__device__ float         g_Opart[NSPLIT * NK * NB * GA];
__device__ float         g_lsum[NSPLIT * NK * NB];

// ---------------- helpers ----------------
__device__ __forceinline__ float2 ffma2(float2 a, float2 b, float2 c) {
    unsigned long long ua = *reinterpret_cast<unsigned long long*>(&a);
    unsigned long long ub = *reinterpret_cast<unsigned long long*>(&b);
    unsigned long long uc = *reinterpret_cast<unsigned long long*>(&c);
    unsigned long long ud;
    asm("fma.rn.f32x2 %0, %1, %2, %3;" : "=l"(ud) : "l"(ua), "l"(ub), "l"(uc));
    return *reinterpret_cast<float2*>(&ud);
}
__device__ __forceinline__ void cp16(uint32_t sdst, const void* gsrc) {
    asm volatile("cp.async.cg.shared.global [%0], [%1], 16;" :: "r"(sdst), "l"(gsrc));
}
#define CP_COMMIT() asm volatile("cp.async.commit_group;" ::: "memory")
#define CP_WAIT(n)  asm volatile("cp.async.wait_group %0;" :: "n"(n) : "memory")

__device__ __forceinline__ void ldsm4(uint32_t* r, uint32_t addr) {
    asm volatile("ldmatrix.sync.aligned.m8n8.x4.shared.b16 {%0,%1,%2,%3}, [%4];"
        : "=r"(r[0]), "=r"(r[1]), "=r"(r[2]), "=r"(r[3]) : "r"(addr));
}
__device__ __forceinline__ void mma16816(float* d, const uint32_t* a,
                                         uint32_t b0, uint32_t b1) {
    asm volatile("mma.sync.aligned.m16n8k16.row.col.f32.bf16.bf16.f32 "
        "{%0,%1,%2,%3}, {%4,%5,%6,%7}, {%8,%9}, {%0,%1,%2,%3};"
        : "+f"(d[0]), "+f"(d[1]), "+f"(d[2]), "+f"(d[3])
        : "r"(a[0]), "r"(a[1]), "r"(a[2]), "r"(a[3]), "r"(b0), "r"(b1));
}
__device__ __forceinline__ uint32_t packbf(float hi, float lo) {
    uint32_t r;
    asm("cvt.rn.bf16x2.f32 %0, %1, %2;" : "=r"(r) : "f"(hi), "f"(lo));
    return r;
}

// ---------------------------------------------------------------------------
// Encoder: mode 0 -> g_enc_s fp32; mode 1 -> g_Khi/g_Klo bf16 split + norms.
// ---------------------------------------------------------------------------
__global__ __launch_bounds__(256) void encoder_kernel(
    const float* __restrict__ x, int nrows, int mode,
    const float* __restrict__ W0, const float* __restrict__ b0,
    const float* __restrict__ W1, const float* __restrict__ b1,
    const float* __restrict__ W2, const float* __restrict__ b2)
{
    const int k    = blockIdx.y;
    const int row0 = blockIdx.x * 64;
    const int tid  = threadIdx.x;
    const int o    = tid & 63;
    const int rr   = tid >> 6;

    __shared__ float smem[10304];
    float* xs  = smem;
    float* hs0 = smem + 2048;
    float* hs1 = smem + 6144;
    float* hs2 = smem;   // 64*65, aliases xs+hs0 (dead by layer 2)

    for (int i = tid; i < 64 * SDIM; i += 256)
        xs[i] = x[(size_t)row0 * SDIM + i];
    __syncthreads();

    {
        float2 w[SDIM / 2];
        const float* Wp = W0 + (size_t)k * SDIM * HID + o;
        #pragma unroll
        for (int i = 0; i < SDIM / 2; i++)
            w[i] = make_float2(Wp[(2 * i) * HID], Wp[(2 * i + 1) * HID]);
        const float bias = b0[k * HID + o];
        #pragma unroll 4
        for (int r = rr; r < 64; r += 4) {
            const float2* xr = reinterpret_cast<const float2*>(xs + r * SDIM);
            float2 acc = make_float2(0.f, 0.f);
            #pragma unroll
            for (int i = 0; i < SDIM / 2; i++) acc = ffma2(xr[i], w[i], acc);
            hs0[r * HID + o] = fmaxf(acc.x + acc.y + bias, 0.f);
        }
    }
    __syncthreads();
    {
        float2 w[HID / 2];
        const float* Wp = W1 + (size_t)k * HID * HID + o;
        #pragma unroll
        for (int i = 0; i < HID / 2; i++)
            w[i] = make_float2(Wp[(2 * i) * HID], Wp[(2 * i + 1) * HID]);
        const float bias = b1[k * HID + o];
        #pragma unroll 4
        for (int r = rr; r < 64; r += 4) {
            const float2* hr = reinterpret_cast<const float2*>(hs0 + r * HID);
            float2 acc = make_float2(0.f, 0.f);
            #pragma unroll
            for (int i = 0; i < HID / 2; i++) acc = ffma2(hr[i], w[i], acc);
            hs1[r * HID + o] = fmaxf(acc.x + acc.y + bias, 0.f);
        }
    }
    __syncthreads();
    {
        float2 w[HID / 2];
        const float* Wp = W2 + (size_t)k * HID * HID + o;
        #pragma unroll
        for (int i = 0; i < HID / 2; i++)
            w[i] = make_float2(Wp[(2 * i) * HID], Wp[(2 * i + 1) * HID]);
        const float bias = b2[k * HID + o];
        #pragma unroll 4
        for (int r = rr; r < 64; r += 4) {
            const float2* hr = reinterpret_cast<const float2*>(hs1 + r * HID);
            float2 acc = make_float2(0.f, 0.f);
            #pragma unroll
            for (int i = 0; i < HID / 2; i++) acc = ffma2(hr[i], w[i], acc);
            hs2[r * 65 + o] = fmaxf(acc.x + acc.y + bias, 0.f);
        }
    }
    __syncthreads();

    if (mode == 0) {
        for (int i = tid; i < 64 * 64; i += 256) {
            int row = i >> 6, d = i & 63;
            g_enc_s[((size_t)k * NB + row0 + row) * HID + d] = hs2[row * 65 + d];
        }
    } else {
        for (int i = tid; i < 64 * 64; i += 256) {
            int row = i >> 6, d = i & 63;
            float f = hs2[row * 65 + d];
            __nv_bfloat16 h = __float2bfloat16(f);
            __nv_bfloat16 lo = __float2bfloat16(f - __bfloat162float(h));
            size_t idx = ((size_t)k * NH + row0 + row) * HID + d;
            g_Khi[idx] = h;
            g_Klo[idx] = lo;
        }
        if (tid < 64) {
            float ss = 0.f;
            #pragma unroll 8
            for (int d = 0; d < HID; d++) {
                float v = hs2[tid * 65 + d];
                ss += v * v;
            }
            atomicMax((int*)&g_Kmax[k], __float_as_int(sqrtf(ss)));
        }
    }
}

// ---------------------------------------------------------------------------
// V transpose + bf16 split: g_VThi/lo[a][j] = split(V[j][a])
// ---------------------------------------------------------------------------
__global__ __launch_bounds__(256) void vtrans_kernel(const float* __restrict__ V)
{
    __shared__ float sm[128 * GA];
    const int j0 = blockIdx.x * 128;
    for (int i = threadIdx.x; i < 128 * GA; i += 256)
        sm[i] = V[(size_t)j0 * GA + i];
    __syncthreads();
    for (int i = threadIdx.x; i < 128 * GA; i += 256) {
        int a = i >> 7, j = i & 127;
        float f = sm[j * GA + a];
        __nv_bfloat16 h = __float2bfloat16(f);
        __nv_bfloat16 lo = __float2bfloat16(f - __bfloat162float(h));
        g_VThi[(size_t)a * NH + j0 + j] = h;
        g_VTlo[(size_t)a * NH + j0 + j] = lo;
    }
}

// ---------------------------------------------------------------------------
// mma.sync flash attention. Grid (8 qtiles, NK, NSPLIT), 256 threads, 8 warps.
// Warp w owns queries 16w..16w+15. Fixed softmax bound m-hat (no rescaling).
// ---------------------------------------------------------------------------
__device__ __forceinline__ void load_tile(uint32_t sb, int k, int key0, int buf,
                                          int tid)
{
    const uint32_t kh = sb + (buf ? SM_KH1 : SM_KH0);
    const uint32_t kl = sb + (buf ? SM_KL1 : SM_KL0);
    const char* shi = (const char*)(g_Khi + ((size_t)k * NH + key0) * HID);
    const char* slo = (const char*)(g_Klo + ((size_t)k * NH + key0) * HID);
    #pragma unroll
    for (int it = 0; it < 4; it++) {
        int idx = tid + it * 256;               // 0..1023
        int row = idx >> 3, c = idx & 7;
        uint32_t doff = row * KROWB + c * 16;
        size_t goff = (size_t)row * 128 + c * 16;
        cp16(kh + doff, shi + goff);
        cp16(kl + doff, slo + goff);
    }
    const uint32_t vh = sb + (buf ? SM_VH1 : SM_VH0);
    const uint32_t vl = sb + (buf ? SM_VL1 : SM_VL0);
    const char* vhi = (const char*)g_VThi + (size_t)key0 * 2;
    const char* vlo = (const char*)g_VTlo + (size_t)key0 * 2;
    #pragma unroll
    for (int it = 0; it < 5; it++) {
        int idx = tid + it * 256;               // 0..1279
        int a = idx >> 4, c = idx & 15;
        uint32_t doff = a * VROWB + c * 16;
        size_t goff = (size_t)a * NH * 2 + c * 16;
        cp16(vh + doff, vhi + goff);
        cp16(vl + doff, vlo + goff);
    }
}

__global__ __launch_bounds__(256, 1) void attn_kernel()
{
    extern __shared__ char smem[];
    const uint32_t sb = (uint32_t)__cvta_generic_to_shared(smem);
    const int tid  = threadIdx.x;
    const int warp = tid >> 5;
    const int lane = tid & 31;
    const int k    = blockIdx.y;
    const int sp   = blockIdx.z;
    const int q0   = blockIdx.x * MQ;
    const int kb0  = sp * KEYS_PER_CTA;

    const float* Qg = g_enc_s + ((size_t)k * NB + q0) * HID;
    float* MH = (float*)(smem + SM_MHAT);

    // m-hat per query row
    if (tid < MQ) {
        const float4* qr = (const float4*)(Qg + tid * HID);
        float ss = 0.f;
        #pragma unroll
        for (int i = 0; i < 16; i++) {
            float4 f = qr[i];
            ss += f.x * f.x + f.y * f.y + f.z * f.z + f.w * f.w;
        }
        MH[tid] = sqrtf(ss) * g_Kmax[k];
    }

    // stage Q (bf16 hi/lo) into KH0/KL0 buffers, then extract fragments
    {
        int row = tid >> 1, half = tid & 1;
        const float* qr = Qg + row * HID + half * 32;
        char* dh = smem + SM_KH0 + row * KROWB + half * 64;
        char* dl = smem + SM_KL0 + row * KROWB + half * 64;
        #pragma unroll
        for (int i = 0; i < 8; i++) {
            float4 f = *(const float4*)(qr + i * 4);
            uint32_t h0 = packbf(f.y, f.x);
            uint32_t h1 = packbf(f.w, f.z);
            float r0 = f.x - __uint_as_float(h0 << 16);
            float r1 = f.y - __uint_as_float(h0 & 0xffff0000u);
            float r2 = f.z - __uint_as_float(h1 << 16);
            float r3 = f.w - __uint_as_float(h1 & 0xffff0000u);
            *(uint32_t*)(dh + i * 8)     = h0;
            *(uint32_t*)(dh + i * 8 + 4) = h1;
            *(uint32_t*)(dl + i * 8)     = packbf(r1, r0);
            *(uint32_t*)(dl + i * 8 + 4) = packbf(r3, r2);
        }
    }
    __syncthreads();

    uint32_t qh[4][4], ql[4][4];
    {
        uint32_t ro = (16 * warp + (lane & 15)) * KROWB;
        #pragma unroll
        for (int kk = 0; kk < 4; kk++) {
            uint32_t co = (kk * 16 + ((lane >> 4) & 1) * 8) * 2;
            ldsm4(qh[kk], sb + SM_KH0 + ro + co);
            ldsm4(ql[kk], sb + SM_KL0 + ro + co);
        }
    }
    const float mh0 = MH[16 * warp + (lane >> 2)];
    const float mh1 = MH[16 * warp + (lane >> 2) + 8];
    __syncthreads();   // Q buffers now free for K tiles

    // prologue: tile 0 into buffer 0
    load_tile(sb, k, kb0, 0, tid);
    CP_COMMIT();

    float oacc[10][4];
    #pragma unroll
    for (int ab = 0; ab < 10; ab++)
        #pragma unroll
        for (int e = 0; e < 4; e++) oacc[ab][e] = 0.f;
    float lacc0 = 0.f, lacc1 = 0.f;

    const uint32_t lr8 = (lane & 7), lc8 = ((lane >> 3) & 3);

    for (int t = 0; t < TILES; t++) {
        if (t + 1 < TILES) {
            load_tile(sb, k, kb0 + (t + 1) * KT, (t + 1) & 1, tid);
            CP_COMMIT();
            CP_WAIT(1);
        } else {
            CP_WAIT(0);
        }
        __syncthreads();

        const uint32_t KH = sb + ((t & 1) ? SM_KH1 : SM_KH0);
        const uint32_t KL = sb + ((t & 1) ? SM_KL1 : SM_KL0);
        const uint32_t VH = sb + ((t & 1) ? SM_VH1 : SM_VH0);
        const uint32_t VL = sb + ((t & 1) ? SM_VL1 : SM_VL0);

        // ---- scores: S = QhiKhi + QloKhi + QhiKlo ----
        float sacc[16][4];
        #pragma unroll
        for (int nb2 = 0; nb2 < 8; nb2++) {
            const int n0 = 2 * nb2, n1 = n0 + 1;
            #pragma unroll
            for (int e = 0; e < 4; e++) { sacc[n0][e] = 0.f; sacc[n1][e] = 0.f; }
            #pragma unroll
            for (int dp = 0; dp < 2; dp++) {
                const uint32_t co = (dp * 32 + lc8 * 8) * 2;
                uint32_t bh0[4], bl0[4], bh1[4], bl1[4];
                ldsm4(bh0, KH + (n0 * 8 + lr8) * KROWB + co);
                ldsm4(bh1, KH + (n1 * 8 + lr8) * KROWB + co);
                ldsm4(bl0, KL + (n0 * 8 + lr8) * KROWB + co);
                ldsm4(bl1, KL + (n1 * 8 + lr8) * KROWB + co);
                const int k0 = 2 * dp, k1 = 2 * dp + 1;
                mma16816(sacc[n0], qh[k0], bh0[0], bh0[1]);
                mma16816(sacc[n1], qh[k0], bh1[0], bh1[1]);
                mma16816(sacc[n0], qh[k1], bh0[2], bh0[3]);
                mma16816(sacc[n1], qh[k1], bh1[2], bh1[3]);
                mma16816(sacc[n0], ql[k0], bh0[0], bh0[1]);
                mma16816(sacc[n1], ql[k0], bh1[0], bh1[1]);
                mma16816(sacc[n0], ql[k1], bh0[2], bh0[3]);
                mma16816(sacc[n1], ql[k1], bh1[2], bh1[3]);
                mma16816(sacc[n0], qh[k0], bl0[0], bl0[1]);
                mma16816(sacc[n1], qh[k0], bl1[0], bl1[1]);
                mma16816(sacc[n0], qh[k1], bl0[2], bl0[3]);
                mma16816(sacc[n1], qh[k1], bl1[2], bl1[3]);
            }
        }

        // ---- softmax with fixed bound: p = exp(s - mh) ----
        #pragma unroll
        for (int nb = 0; nb < 16; nb++) {
            float p0 = __expf(sacc[nb][0] - mh0);
            float p1 = __expf(sacc[nb][1] - mh0);
            float p2 = __expf(sacc[nb][2] - mh1);
            float p3 = __expf(sacc[nb][3] - mh1);
            lacc0 += p0 + p1;
            lacc1 += p2 + p3;
            sacc[nb][0] = p0; sacc[nb][1] = p1;
            sacc[nb][2] = p2; sacc[nb][3] = p3;
        }

        // ---- PV: O += PhiVhi + PloVhi + PhiVlo ----
        #pragma unroll
        for (int jp = 0; jp < 4; jp++) {
            uint32_t ah[2][4], al[2][4];
            #pragma unroll
            for (int m = 0; m < 2; m++) {
                const int nA = 4 * jp + 2 * m;
                #pragma unroll
                for (int h = 0; h < 2; h++) {
                    float c0 = sacc[nA + h][0], c1 = sacc[nA + h][1];
                    float c2 = sacc[nA + h][2], c3 = sacc[nA + h][3];
                    uint32_t h01 = packbf(c1, c0);
                    uint32_t h23 = packbf(c3, c2);
                    ah[m][2 * h]     = h01;
                    ah[m][2 * h + 1] = h23;
                    float r0 = c0 - __uint_as_float(h01 << 16);
                    float r1 = c1 - __uint_as_float(h01 & 0xffff0000u);
                    float r2 = c2 - __uint_as_float(h23 << 16);
                    float r3 = c3 - __uint_as_float(h23 & 0xffff0000u);
                    al[m][2 * h]     = packbf(r1, r0);
                    al[m][2 * h + 1] = packbf(r3, r2);
                }
            }
            const uint32_t co = (jp * 32 + lc8 * 8) * 2;
            #pragma unroll
            for (int ab2 = 0; ab2 < 5; ab2++) {
                const int a0 = 2 * ab2, a1 = a0 + 1;
                uint32_t vh0[4], vh1[4], vl0[4], vl1[4];
                ldsm4(vh0, VH + (a0 * 8 + lr8) * VROWB + co);
                ldsm4(vh1, VH + (a1 * 8 + lr8) * VROWB + co);
                mma16816(oacc[a0], ah[0], vh0[0], vh0[1]);
                mma16816(oacc[a1], ah[0], vh1[0], vh1[1]);
                mma16816(oacc[a0], ah[1], vh0[2], vh0[3]);
                mma16816(oacc[a1], ah[1], vh1[2], vh1[3]);
                mma16816(oacc[a0], al[0], vh0[0], vh0[1]);
                mma16816(oacc[a1], al[0], vh1[0], vh1[1]);
                mma16816(oacc[a0], al[1], vh0[2], vh0[3]);
                mma16816(oacc[a1], al[1], vh1[2], vh1[3]);
                ldsm4(vl0, VL + (a0 * 8 + lr8) * VROWB + co);
                ldsm4(vl1, VL + (a1 * 8 + lr8) * VROWB + co);
                mma16816(oacc[a0], ah[0], vl0[0], vl0[1]);
                mma16816(oacc[a1], ah[0], vl1[0], vl1[1]);
                mma16816(oacc[a0], ah[1], vl0[2], vl0[3]);
                mma16816(oacc[a1], ah[1], vl1[2], vl1[3]);
            }
        }
        __syncthreads();
    }

    // ---- epilogue: write unnormalized O + l ----
    const int r  = lane >> 2, tq = lane & 3;
    const int qrow0 = q0 + 16 * warp + r;
    const int qrow1 = qrow0 + 8;
    float* Ob = g_Opart + ((size_t)sp * NK + k) * NB * GA;
    #pragma unroll
    for (int ab = 0; ab < 10; ab++) {
        const int col = ab * 8 + tq * 2;
        Ob[(size_t)qrow0 * GA + col]     = oacc[ab][0];
        Ob[(size_t)qrow0 * GA + col + 1] = oacc[ab][1];
        Ob[(size_t)qrow1 * GA + col]     = oacc[ab][2];
        Ob[(size_t)qrow1 * GA + col + 1] = oacc[ab][3];
    }
    lacc0 += __shfl_xor_sync(0xffffffffu, lacc0, 1);
    lacc0 += __shfl_xor_sync(0xffffffffu, lacc0, 2);
    lacc1 += __shfl_xor_sync(0xffffffffu, lacc1, 1);
    lacc1 += __shfl_xor_sync(0xffffffffu, lacc1, 2);
    if (tq == 0) {
        float* Lb = g_lsum + ((size_t)sp * NK + k) * NB;
        Lb[qrow0] = lacc0;
        Lb[qrow1] = lacc1;
    }
}

// ---------------------------------------------------------------------------
// Merge: sum splits (shared m-hat => plain sums), normalize, k-combine.
// ---------------------------------------------------------------------------
__global__ __launch_bounds__(256) void merge_kernel(
    const float* __restrict__ assign, float* __restrict__ out)
{
    int idx = blockIdx.x * 256 + threadIdx.x;
    if (idx >= NB * GA) return;
    int b  = idx / GA;
    int ga = idx - b * GA;
    int g  = ga >> 3;

    float aw[NK], mxw = -CUDART_INF_F;
    #pragma unroll
    for (int k = 0; k < NK; k++) {
        aw[k] = __ldg(assign + g * NK + k);
        mxw = fmaxf(mxw, aw[k]);
    }
    float wsum = 0.f;
    #pragma unroll
    for (int k = 0; k < NK; k++) { aw[k] = __expf(aw[k] - mxw); wsum += aw[k]; }
    float winv = 1.f / wsum;

    float acc = 0.f;
    #pragma unroll
    for (int k = 0; k < NK; k++) {
        float O = 0.f, L = 0.f;
        #pragma unroll
        for (int s = 0; s < NSPLIT; s++) {
            O += g_Opart[(((size_t)s * NK + k) * NB + b) * GA + ga];
            L += g_lsum[((size_t)s * NK + k) * NB + b];
        }
        acc += aw[k] * (O / L);
    }
    out[idx] = acc * winv;
}

// ---------------------------------------------------------------------------
extern "C" void kernel_launch(void* const* d_in, const int* in_sizes, int n_in,
                              void* d_out, int out_size)
{
    (void)in_sizes; (void)n_in; (void)out_size;
    const float* state  = (const float*)d_in[0];
    const float* hist   = (const float*)d_in[1];
    const float* jah    = (const float*)d_in[2];
    const float* W0 = (const float*)d_in[3];
    const float* b0 = (const float*)d_in[4];
    const float* W1 = (const float*)d_in[5];
    const float* b1 = (const float*)d_in[6];
    const float* W2 = (const float*)d_in[7];
    const float* b2 = (const float*)d_in[8];
    const float* assign = (const float*)d_in[9];
    float* out = (float*)d_out;

    vtrans_kernel<<<NH / 128, 256>>>(jah);
    encoder_kernel<<<dim3(NH / 64, NK), 256>>>(hist, NH, 1,
                                               W0, b0, W1, b1, W2, b2);
    encoder_kernel<<<dim3(NB / 64, NK), 256>>>(state, NB, 0,
                                               W0, b0, W1, b1, W2, b2);

    cudaFuncSetAttribute(attn_kernel,
                         cudaFuncAttributeMaxDynamicSharedMemorySize, SM_TOTAL);
    attn_kernel<<<dim3(NB / MQ, NK, NSPLIT), 256, SM_TOTAL>>>();

    merge_kernel<<<(NB * GA + 255) / 256, 256>>>(assign, out);
}

// round 10
// speedup vs baseline: 4.0944x; 1.0105x over previous
#include <cuda_runtime.h>
#include <cuda_bf16.h>
#include <math_constants.h>
#include <cstdint>

#define NB   1024
#define NH   16384
#define SDIM 32
#define HID  64
#define NK   4
#define GA   80

#define MQ   256
#define KT   128
#define NSPLIT 8
#define KEYS_PER_CTA (NH / NSPLIT)   // 2048
#define TILES (KEYS_PER_CTA / KT)    // 16
#define ATHR 512

#define KROWB 144    // K/Q smem row stride bytes (64 bf16 + 16B pad)
#define VROWB 272    // V smem row stride bytes (128 bf16 + 16B pad)

// smem byte offsets
#define SM_MHAT 0                            // 256 floats
#define SM_QLO  1024                         // 256 * KROWB = 36864
#define SM_KH0  (SM_QLO + 256 * KROWB)       // 37888
#define SM_QHI  SM_KH0                       // Q-hi staging aliases KH0+KL0 (256 rows)
#define SM_KL0  (SM_KH0 + 128 * KROWB)       // 56320
#define SM_KH1  (SM_KL0 + 128 * KROWB)       // 74752
#define SM_KL1  (SM_KH1 + 128 * KROWB)       // 93184
#define SM_VH0  (SM_KL1 + 128 * KROWB)       // 111616
#define SM_VL0  (SM_VH0 + 80 * VROWB)        // 133376
#define SM_VH1  (SM_VL0 + 80 * VROWB)        // 155136
#define SM_VL1  (SM_VH1 + 80 * VROWB)        // 176896
#define SM_TOTAL (SM_VL1 + 80 * VROWB)       // 198656

// global scratch
__device__ float         g_enc_s[NK * NB * HID];
__device__ __nv_bfloat16 g_Khi[NK * NH * HID];
__device__ __nv_bfloat16 g_Klo[NK * NH * HID];
__device__ __nv_bfloat16 g_VThi[GA * NH];
__device__ __nv_bfloat16 g_VTlo[GA * NH];
__device__ float         g_Kmax[NK];
__device__ float         g_Opart[NSPLIT * NK * NB * GA];
__device__ float         g_lsum[NSPLIT * NK * NB];

// ---------------- helpers ----------------
__device__ __forceinline__ float2 ffma2(float2 a, float2 b, float2 c) {
    unsigned long long ua = *reinterpret_cast<unsigned long long*>(&a);
    unsigned long long ub = *reinterpret_cast<unsigned long long*>(&b);
    unsigned long long uc = *reinterpret_cast<unsigned long long*>(&c);
    unsigned long long ud;
    asm("fma.rn.f32x2 %0, %1, %2, %3;" : "=l"(ud) : "l"(ua), "l"(ub), "l"(uc));
    return *reinterpret_cast<float2*>(&ud);
}
__device__ __forceinline__ void cp16(uint32_t sdst, const void* gsrc) {
    asm volatile("cp.async.cg.shared.global [%0], [%1], 16;" :: "r"(sdst), "l"(gsrc));
}
#define CP_COMMIT() asm volatile("cp.async.commit_group;" ::: "memory")
#define CP_WAIT(n)  asm volatile("cp.async.wait_group %0;" :: "n"(n) : "memory")

__device__ __forceinline__ void ldsm4(uint32_t* r, uint32_t addr) {
    asm volatile("ldmatrix.sync.aligned.m8n8.x4.shared.b16 {%0,%1,%2,%3}, [%4];"
        : "=r"(r[0]), "=r"(r[1]), "=r"(r[2]), "=r"(r[3]) : "r"(addr));
}
__device__ __forceinline__ void mma16816(float* d, const uint32_t* a,
                                         uint32_t b0, uint32_t b1) {
    asm volatile("mma.sync.aligned.m16n8k16.row.col.f32.bf16.bf16.f32 "
        "{%0,%1,%2,%3}, {%4,%5,%6,%7}, {%8,%9}, {%0,%1,%2,%3};"
        : "+f"(d[0]), "+f"(d[1]), "+f"(d[2]), "+f"(d[3])
        : "r"(a[0]), "r"(a[1]), "r"(a[2]), "r"(a[3]), "r"(b0), "r"(b1));
}
__device__ __forceinline__ uint32_t packbf(float hi, float lo) {
    uint32_t r;
    asm("cvt.rn.bf16x2.f32 %0, %1, %2;" : "=r"(r) : "f"(hi), "f"(lo));
    return r;
}

// ---------------------------------------------------------------------------
// Encoder: mode 0 -> g_enc_s fp32; mode 1 -> g_Khi/g_Klo bf16 split + norms.
// ---------------------------------------------------------------------------
__global__ __launch_bounds__(256) void encoder_kernel(
    const float* __restrict__ x, int nrows, int mode,
    const float* __restrict__ W0, const float* __restrict__ b0,
    const float* __restrict__ W1, const float* __restrict__ b1,
    const float* __restrict__ W2, const float* __restrict__ b2)
{
    const int k    = blockIdx.y;
    const int row0 = blockIdx.x * 64;
    const int tid  = threadIdx.x;
    const int o    = tid & 63;
    const int rr   = tid >> 6;

    __shared__ float smem[10304];
    float* xs  = smem;
    float* hs0 = smem + 2048;
    float* hs1 = smem + 6144;
    float* hs2 = smem;   // 64*65, aliases xs+hs0 (dead by layer 2)

    for (int i = tid; i < 64 * SDIM; i += 256)
        xs[i] = x[(size_t)row0 * SDIM + i];
    __syncthreads();

    {
        float2 w[SDIM / 2];
        const float* Wp = W0 + (size_t)k * SDIM * HID + o;
        #pragma unroll
        for (int i = 0; i < SDIM / 2; i++)
            w[i] = make_float2(Wp[(2 * i) * HID], Wp[(2 * i + 1) * HID]);
        const float bias = b0[k * HID + o];
        #pragma unroll 4
        for (int r = rr; r < 64; r += 4) {
            const float2* xr = reinterpret_cast<const float2*>(xs + r * SDIM);
            float2 acc = make_float2(0.f, 0.f);
            #pragma unroll
            for (int i = 0; i < SDIM / 2; i++) acc = ffma2(xr[i], w[i], acc);
            hs0[r * HID + o] = fmaxf(acc.x + acc.y + bias, 0.f);
        }
    }
    __syncthreads();
    {
        float2 w[HID / 2];
        const float* Wp = W1 + (size_t)k * HID * HID + o;
        #pragma unroll
        for (int i = 0; i < HID / 2; i++)
            w[i] = make_float2(Wp[(2 * i) * HID], Wp[(2 * i + 1) * HID]);
        const float bias = b1[k * HID + o];
        #pragma unroll 4
        for (int r = rr; r < 64; r += 4) {
            const float2* hr = reinterpret_cast<const float2*>(hs0 + r * HID);
            float2 acc = make_float2(0.f, 0.f);
            #pragma unroll
            for (int i = 0; i < HID / 2; i++) acc = ffma2(hr[i], w[i], acc);
            hs1[r * HID + o] = fmaxf(acc.x + acc.y + bias, 0.f);
        }
    }
    __syncthreads();
    {
        float2 w[HID / 2];
        const float* Wp = W2 + (size_t)k * HID * HID + o;
        #pragma unroll
        for (int i = 0; i < HID / 2; i++)
            w[i] = make_float2(Wp[(2 * i) * HID], Wp[(2 * i + 1) * HID]);
        const float bias = b2[k * HID + o];
        #pragma unroll 4
        for (int r = rr; r < 64; r += 4) {
            const float2* hr = reinterpret_cast<const float2*>(hs1 + r * HID);
            float2 acc = make_float2(0.f, 0.f);
            #pragma unroll
            for (int i = 0; i < HID / 2; i++) acc = ffma2(hr[i], w[i], acc);
            hs2[r * 65 + o] = fmaxf(acc.x + acc.y + bias, 0.f);
        }
    }
    __syncthreads();

    if (mode == 0) {
        for (int i = tid; i < 64 * 64; i += 256) {
            int row = i >> 6, d = i & 63;
            g_enc_s[((size_t)k * NB + row0 + row) * HID + d] = hs2[row * 65 + d];
        }
    } else {
        for (int i = tid; i < 64 * 64; i += 256) {
            int row = i >> 6, d = i & 63;
            float f = hs2[row * 65 + d];
            __nv_bfloat16 h = __float2bfloat16(f);
            __nv_bfloat16 lo = __float2bfloat16(f - __bfloat162float(h));
            size_t idx = ((size_t)k * NH + row0 + row) * HID + d;
            g_Khi[idx] = h;
            g_Klo[idx] = lo;
        }
        if (tid < 64) {
            float ss = 0.f;
            #pragma unroll 8
            for (int d = 0; d < HID; d++) {
                float v = hs2[tid * 65 + d];
                ss += v * v;
            }
            atomicMax((int*)&g_Kmax[k], __float_as_int(sqrtf(ss)));
        }
    }
}

// ---------------------------------------------------------------------------
// V transpose + bf16 split: g_VThi/lo[a][j] = split(V[j][a])
// ---------------------------------------------------------------------------
__global__ __launch_bounds__(256) void vtrans_kernel(const float* __restrict__ V)
{
    __shared__ float sm[128 * GA];
    const int j0 = blockIdx.x * 128;
    for (int i = threadIdx.x; i < 128 * GA; i += 256)
        sm[i] = V[(size_t)j0 * GA + i];
    __syncthreads();
    for (int i = threadIdx.x; i < 128 * GA; i += 256) {
        int a = i >> 7, j = i & 127;
        float f = sm[j * GA + a];
        __nv_bfloat16 h = __float2bfloat16(f);
        __nv_bfloat16 lo = __float2bfloat16(f - __bfloat162float(h));
        g_VThi[(size_t)a * NH + j0 + j] = h;
        g_VTlo[(size_t)a * NH + j0 + j] = lo;
    }
}

// ---------------------------------------------------------------------------
// mma.sync flash attention. Grid (4 qtiles, NK, NSPLIT), 512 threads, 16 warps.
// Warp w owns queries 16w..16w+15. Fixed softmax bound (no rescaling).
// S computed in two 64-key halves to cut live registers (128-reg cap).
// ---------------------------------------------------------------------------
__device__ __forceinline__ void load_tile(uint32_t sb, int k, int key0, int buf,
                                          int tid)
{
    const uint32_t kh = sb + (buf ? SM_KH1 : SM_KH0);
    const uint32_t kl = sb + (buf ? SM_KL1 : SM_KL0);
    const char* shi = (const char*)(g_Khi + ((size_t)k * NH + key0) * HID);
    const char* slo = (const char*)(g_Klo + ((size_t)k * NH + key0) * HID);
    #pragma unroll
    for (int it = 0; it < 2; it++) {
        int idx = tid + it * ATHR;              // 0..1023
        int row = idx >> 3, c = idx & 7;
        uint32_t doff = row * KROWB + c * 16;
        size_t goff = (size_t)row * 128 + c * 16;
        cp16(kh + doff, shi + goff);
        cp16(kl + doff, slo + goff);
    }
    const uint32_t vh = sb + (buf ? SM_VH1 : SM_VH0);
    const uint32_t vl = sb + (buf ? SM_VL1 : SM_VL0);
    const char* vhi = (const char*)g_VThi + (size_t)key0 * 2;
    const char* vlo = (const char*)g_VTlo + (size_t)key0 * 2;
    #pragma unroll
    for (int it = 0; it < 3; it++) {
        int idx = tid + it * ATHR;              // 0..1535, need 1280
        if (idx < 1280) {
            int a = idx >> 4, c = idx & 15;
            uint32_t doff = a * VROWB + c * 16;
            size_t goff = (size_t)a * NH * 2 + c * 16;
            cp16(vh + doff, vhi + goff);
            cp16(vl + doff, vlo + goff);
        }
    }
}

__global__ __launch_bounds__(ATHR, 1) void attn_kernel()
{
    extern __shared__ char smem[];
    const uint32_t sb = (uint32_t)__cvta_generic_to_shared(smem);
    const int tid  = threadIdx.x;
    const int warp = tid >> 5;
    const int lane = tid & 31;
    const int k    = blockIdx.y;
    const int sp   = blockIdx.z;
    const int q0   = blockIdx.x * MQ;
    const int kb0  = sp * KEYS_PER_CTA;

    const float* Qg = g_enc_s + ((size_t)k * NB + q0) * HID;
    float* MH = (float*)(smem + SM_MHAT);

    // m-hat per query row (fixed softmax bound)
    if (tid < MQ) {
        const float4* qr = (const float4*)(Qg + tid * HID);
        float ss = 0.f;
        #pragma unroll
        for (int i = 0; i < 16; i++) {
            float4 f = qr[i];
            ss += f.x * f.x + f.y * f.y + f.z * f.z + f.w * f.w;
        }
        MH[tid] = sqrtf(ss) * g_Kmax[k];
    }

    // stage Q: hi into SM_QHI (aliases K buf0, 256 rows), lo into SM_QLO
    {
        int row = tid >> 1, half = tid & 1;
        const float* qr = Qg + row * HID + half * 32;
        char* dh = smem + SM_QHI + row * KROWB + half * 64;
        char* dl = smem + SM_QLO + row * KROWB + half * 64;
        #pragma unroll
        for (int i = 0; i < 8; i++) {
            float4 f = *(const float4*)(qr + i * 4);
            uint32_t h0 = packbf(f.y, f.x);
            uint32_t h1 = packbf(f.w, f.z);
            float r0 = f.x - __uint_as_float(h0 << 16);
            float r1 = f.y - __uint_as_float(h0 & 0xffff0000u);
            float r2 = f.z - __uint_as_float(h1 << 16);
            float r3 = f.w - __uint_as_float(h1 & 0xffff0000u);
            *(uint32_t*)(dh + i * 8)     = h0;
            *(uint32_t*)(dh + i * 8 + 4) = h1;
            *(uint32_t*)(dl + i * 8)     = packbf(r1, r0);
            *(uint32_t*)(dl + i * 8 + 4) = packbf(r3, r2);
        }
    }
    __syncthreads();

    // Q-hi fragments to registers (Q-lo stays resident in SM_QLO)
    uint32_t qh[4][4];
    const uint32_t qro = (16 * warp + (lane & 15)) * KROWB;
    const uint32_t qsel = ((lane >> 4) & 1) * 8;
    #pragma unroll
    for (int kk = 0; kk < 4; kk++)
        ldsm4(qh[kk], sb + SM_QHI + qro + (kk * 16 + qsel) * 2);
    const float mh0 = MH[16 * warp + (lane >> 2)];
    const float mh1 = MH[16 * warp + (lane >> 2) + 8];
    __syncthreads();   // Q-hi staging area now free for K tiles

    load_tile(sb, k, kb0, 0, tid);
    CP_COMMIT();

    float oacc[10][4];
    #pragma unroll
    for (int ab = 0; ab < 10; ab++)
        #pragma unroll
        for (int e = 0; e < 4; e++) oacc[ab][e] = 0.f;
    float lacc0 = 0.f, lacc1 = 0.f;

    const uint32_t lr8 = (lane & 7), lc8 = ((lane >> 3) & 3);

    for (int t = 0; t < TILES; t++) {
        if (t + 1 < TILES) {
            load_tile(sb, k, kb0 + (t + 1) * KT, (t + 1) & 1, tid);
            CP_COMMIT();
            CP_WAIT(1);
        } else {
            CP_WAIT(0);
        }
        __syncthreads();

        const uint32_t KH = sb + ((t & 1) ? SM_KH1 : SM_KH0);
        const uint32_t KL = sb + ((t & 1) ? SM_KL1 : SM_KL0);
        const uint32_t VH = sb + ((t & 1) ? SM_VH1 : SM_VH0);
        const uint32_t VL = sb + ((t & 1) ? SM_VL1 : SM_VL0);

        #pragma unroll
        for (int hf = 0; hf < 2; hf++) {
            // ---- scores for 64-key half: S = QhiKhi + QloKhi + QhiKlo ----
            float sacc[8][4];
            #pragma unroll
            for (int nb = 0; nb < 8; nb++)
                #pragma unroll
                for (int e = 0; e < 4; e++) sacc[nb][e] = 0.f;

            #pragma unroll
            for (int dp = 0; dp < 2; dp++) {
                uint32_t qlA[4], qlB[4];
                ldsm4(qlA, sb + SM_QLO + qro + ((2 * dp) * 16 + qsel) * 2);
                ldsm4(qlB, sb + SM_QLO + qro + ((2 * dp + 1) * 16 + qsel) * 2);
                const uint32_t co = (dp * 32 + lc8 * 8) * 2;
                const int k0 = 2 * dp, k1 = 2 * dp + 1;
                #pragma unroll
                for (int nb2 = 0; nb2 < 4; nb2++) {
                    const int n0 = hf * 8 + 2 * nb2, n1 = n0 + 1;
                    const int l0 = 2 * nb2, l1 = l0 + 1;
                    uint32_t bh0[4], bl0[4], bh1[4], bl1[4];
                    ldsm4(bh0, KH + (n0 * 8 + lr8) * KROWB + co);
                    ldsm4(bh1, KH + (n1 * 8 + lr8) * KROWB + co);
                    ldsm4(bl0, KL + (n0 * 8 + lr8) * KROWB + co);
                    ldsm4(bl1, KL + (n1 * 8 + lr8) * KROWB + co);
                    mma16816(sacc[l0], qh[k0], bh0[0], bh0[1]);
                    mma16816(sacc[l1], qh[k0], bh1[0], bh1[1]);
                    mma16816(sacc[l0], qh[k1], bh0[2], bh0[3]);
                    mma16816(sacc[l1], qh[k1], bh1[2], bh1[3]);
                    mma16816(sacc[l0], qlA, bh0[0], bh0[1]);
                    mma16816(sacc[l1], qlA, bh1[0], bh1[1]);
                    mma16816(sacc[l0], qlB, bh0[2], bh0[3]);
                    mma16816(sacc[l1], qlB, bh1[2], bh1[3]);
                    mma16816(sacc[l0], qh[k0], bl0[0], bl0[1]);
                    mma16816(sacc[l1], qh[k0], bl1[0], bl1[1]);
                    mma16816(sacc[l0], qh[k1], bl0[2], bl0[3]);
                    mma16816(sacc[l1], qh[k1], bl1[2], bl1[3]);
                }
            }

            // ---- softmax with fixed bound ----
            #pragma unroll
            for (int nb = 0; nb < 8; nb++) {
                float p0 = __expf(sacc[nb][0] - mh0);
                float p1 = __expf(sacc[nb][1] - mh0);
                float p2 = __expf(sacc[nb][2] - mh1);
                float p3 = __expf(sacc[nb][3] - mh1);
                lacc0 += p0 + p1;
                lacc1 += p2 + p3;
                sacc[nb][0] = p0; sacc[nb][1] = p1;
                sacc[nb][2] = p2; sacc[nb][3] = p3;
            }

            // ---- PV over this key half: O += PhiVhi + PloVhi + PhiVlo ----
            #pragma unroll
            for (int jp = 0; jp < 2; jp++) {
                uint32_t ah[2][4], al[2][4];
                #pragma unroll
                for (int m = 0; m < 2; m++) {
                    const int nA = 4 * jp + 2 * m;
                    #pragma unroll
                    for (int h = 0; h < 2; h++) {
                        float c0 = sacc[nA + h][0], c1 = sacc[nA + h][1];
                        float c2 = sacc[nA + h][2], c3 = sacc[nA + h][3];
                        uint32_t h01 = packbf(c1, c0);
                        uint32_t h23 = packbf(c3, c2);
                        ah[m][2 * h]     = h01;
                        ah[m][2 * h + 1] = h23;
                        float r0 = c0 - __uint_as_float(h01 << 16);
                        float r1 = c1 - __uint_as_float(h01 & 0xffff0000u);
                        float r2 = c2 - __uint_as_float(h23 << 16);
                        float r3 = c3 - __uint_as_float(h23 & 0xffff0000u);
                        al[m][2 * h]     = packbf(r1, r0);
                        al[m][2 * h + 1] = packbf(r3, r2);
                    }
                }
                const uint32_t co = ((hf * 2 + jp) * 32 + lc8 * 8) * 2;
                #pragma unroll
                for (int ab2 = 0; ab2 < 5; ab2++) {
                    const int a0 = 2 * ab2, a1 = a0 + 1;
                    uint32_t vh0[4], vh1[4], vl0[4], vl1[4];
                    ldsm4(vh0, VH + (a0 * 8 + lr8) * VROWB + co);
                    ldsm4(vh1, VH + (a1 * 8 + lr8) * VROWB + co);
                    mma16816(oacc[a0], ah[0], vh0[0], vh0[1]);
                    mma16816(oacc[a1], ah[0], vh1[0], vh1[1]);
                    mma16816(oacc[a0], ah[1], vh0[2], vh0[3]);
                    mma16816(oacc[a1], ah[1], vh1[2], vh1[3]);
                    mma16816(oacc[a0], al[0], vh0[0], vh0[1]);
                    mma16816(oacc[a1], al[0], vh1[0], vh1[1]);
                    mma16816(oacc[a0], al[1], vh0[2], vh0[3]);
                    mma16816(oacc[a1], al[1], vh1[2], vh1[3]);
                    ldsm4(vl0, VL + (a0 * 8 + lr8) * VROWB + co);
                    ldsm4(vl1, VL + (a1 * 8 + lr8) * VROWB + co);
                    mma16816(oacc[a0], ah[0], vl0[0], vl0[1]);
                    mma16816(oacc[a1], ah[0], vl1[0], vl1[1]);
                    mma16816(oacc[a0], ah[1], vl0[2], vl0[3]);
                    mma16816(oacc[a1], ah[1], vl1[2], vl1[3]);
                }
            }
        }
        __syncthreads();
    }

    // ---- epilogue: write unnormalized O + l ----
    const int r  = lane >> 2, tq = lane & 3;
    const int qrow0 = q0 + 16 * warp + r;
    const int qrow1 = qrow0 + 8;
    float* Ob = g_Opart + ((size_t)sp * NK + k) * NB * GA;
    #pragma unroll
    for (int ab = 0; ab < 10; ab++) {
        const int col = ab * 8 + tq * 2;
        Ob[(size_t)qrow0 * GA + col]     = oacc[ab][0];
        Ob[(size_t)qrow0 * GA + col + 1] = oacc[ab][1];
        Ob[(size_t)qrow1 * GA + col]     = oacc[ab][2];
        Ob[(size_t)qrow1 * GA + col + 1] = oacc[ab][3];
    }
    lacc0 += __shfl_xor_sync(0xffffffffu, lacc0, 1);
    lacc0 += __shfl_xor_sync(0xffffffffu, lacc0, 2);
    lacc1 += __shfl_xor_sync(0xffffffffu, lacc1, 1);
    lacc1 += __shfl_xor_sync(0xffffffffu, lacc1, 2);
    if (tq == 0) {
        float* Lb = g_lsum + ((size_t)sp * NK + k) * NB;
        Lb[qrow0] = lacc0;
        Lb[qrow1] = lacc1;
    }
}

// ---------------------------------------------------------------------------
// Merge: sum splits (shared m-hat => plain sums), normalize, k-combine.
// ---------------------------------------------------------------------------
__global__ __launch_bounds__(256) void merge_kernel(
    const float* __restrict__ assign, float* __restrict__ out)
{
    int idx = blockIdx.x * 256 + threadIdx.x;
    if (idx >= NB * GA) return;
    int b  = idx / GA;
    int ga = idx - b * GA;
    int g  = ga >> 3;

    float aw[NK], mxw = -CUDART_INF_F;
    #pragma unroll
    for (int k = 0; k < NK; k++) {
        aw[k] = __ldg(assign + g * NK + k);
        mxw = fmaxf(mxw, aw[k]);
    }
    float wsum = 0.f;
    #pragma unroll
    for (int k = 0; k < NK; k++) { aw[k] = __expf(aw[k] - mxw); wsum += aw[k]; }
    float winv = 1.f / wsum;

    float acc = 0.f;
    #pragma unroll
    for (int k = 0; k < NK; k++) {
        float O = 0.f, L = 0.f;
        #pragma unroll
        for (int s = 0; s < NSPLIT; s++) {
            O += g_Opart[(((size_t)s * NK + k) * NB + b) * GA + ga];
            L += g_lsum[((size_t)s * NK + k) * NB + b];
        }
        acc += aw[k] * (O / L);
    }
    out[idx] = acc * winv;
}

// ---------------------------------------------------------------------------
extern "C" void kernel_launch(void* const* d_in, const int* in_sizes, int n_in,
                              void* d_out, int out_size)
{
    (void)in_sizes; (void)n_in; (void)out_size;
    const float* state  = (const float*)d_in[0];
    const float* hist   = (const float*)d_in[1];
    const float* jah    = (const float*)d_in[2];
    const float* W0 = (const float*)d_in[3];
    const float* b0 = (const float*)d_in[4];
    const float* W1 = (const float*)d_in[5];
    const float* b1 = (const float*)d_in[6];
    const float* W2 = (const float*)d_in[7];
    const float* b2 = (const float*)d_in[8];
    const float* assign = (const float*)d_in[9];
    float* out = (float*)d_out;

    vtrans_kernel<<<NH / 128, 256>>>(jah);
    encoder_kernel<<<dim3(NH / 64, NK), 256>>>(hist, NH, 1,
                                               W0, b0, W1, b1, W2, b2);
    encoder_kernel<<<dim3(NB / 64, NK), 256>>>(state, NB, 0,
                                               W0, b0, W1, b1, W2, b2);

    cudaFuncSetAttribute(attn_kernel,
                         cudaFuncAttributeMaxDynamicSharedMemorySize, SM_TOTAL);
    attn_kernel<<<dim3(NB / MQ, NK, NSPLIT), ATHR, SM_TOTAL>>>();

    merge_kernel<<<(NB * GA + 255) / 256, 256>>>(assign, out);
}